// round 4
// baseline (speedup 1.0000x reference)
#include <cuda_runtime.h>

#define N_NODES 100000
#define N_EDGES 3200000

// Per-node projected aggregate. Invariant: zero at kernel_launch entry.
// __device__ globals are zero-initialized at load; node_kernel re-zeros
// after consuming, so the invariant holds across graph replays.
__device__ float2 g_z[N_NODES];

__global__ void __launch_bounds__(256) edge_kernel(
    const float4* __restrict__ ea,        // edge_attr as float4[N_EDGES*4]
    const int* __restrict__ col,          // edge_index row 1 (dst), int32
    const float* __restrict__ W1)         // [19,2] row-major
{
    float w0[16], w1[16];
#pragma unroll
    for (int k = 0; k < 16; k++) {
        w0[k] = __ldg(&W1[(3 + k) * 2 + 0]);
        w1[k] = __ldg(&W1[(3 + k) * 2 + 1]);
    }

    int e = blockIdx.x * blockDim.x + threadIdx.x;
    if (e >= N_EDGES) return;

    const float4 a = ea[e * 4 + 0];
    const float4 b = ea[e * 4 + 1];
    const float4 c = ea[e * 4 + 2];
    const float4 d = ea[e * 4 + 3];

    float p0 = a.x * w0[0]  + a.y * w0[1]  + a.z * w0[2]  + a.w * w0[3]
             + b.x * w0[4]  + b.y * w0[5]  + b.z * w0[6]  + b.w * w0[7]
             + c.x * w0[8]  + c.y * w0[9]  + c.z * w0[10] + c.w * w0[11]
             + d.x * w0[12] + d.y * w0[13] + d.z * w0[14] + d.w * w0[15];

    float p1 = a.x * w1[0]  + a.y * w1[1]  + a.z * w1[2]  + a.w * w1[3]
             + b.x * w1[4]  + b.y * w1[5]  + b.z * w1[6]  + b.w * w1[7]
             + c.x * w1[8]  + c.y * w1[9]  + c.z * w1[10] + c.w * w1[11]
             + d.x * w1[12] + d.y * w1[13] + d.z * w1[14] + d.w * w1[15];

    int node = col[e];
    if ((unsigned)node < (unsigned)N_NODES) {
        atomicAdd(&g_z[node], make_float2(p0, p1));  // RED.ADD.F32x2
    }
}

__global__ void __launch_bounds__(256) node_kernel(
    const float* __restrict__ x,
    const float* __restrict__ W1,
    const float* __restrict__ b1,
    const float* __restrict__ W2,
    const float* __restrict__ b2,
    float* __restrict__ out)
{
    const int i = blockIdx.x * blockDim.x + threadIdx.x;
    const bool active = (i < N_NODES);

    float x0 = 0.f, x1 = 0.f, x2 = 0.f;
    if (active) {
        x0 = x[i * 3 + 0];
        x1 = x[i * 3 + 1];
        x2 = x[i * 3 + 2];
    }

    // ---- Everything independent of the edge aggregation (overlaps edge_kernel via PDL) ----
    const float vi = x0, s1 = x1, s2 = x2;

    const float n1 = (__powf(0.7660379f, s2 * (1.0f / 0.3038425f) + s1)
                      + __powf(0.12117091f, s1) * (1.0f / -0.7256157f))
                     * __powf(1.2125463f, vi) + 0.12262904f;

    const float t = s2 + (s1 + (-3.283101f) - vi * (1.0f / 0.79082423f)) * 0.31992579f;
    const float n1_n2 = 0.7872602f - sqrtf(__logf(__powf(0.1562228f, t) + 1.4462701f));

    // x-only part of h
    const float h0x = b1[0] + x0 * W1[0] + x1 * W1[2] + x2 * W1[4];
    const float h1x = b1[1] + x0 * W1[1] + x1 * W1[3] + x2 * W1[5];
    const float w20 = W2[2], w21 = W2[5], bb2 = b2[2];

    // ---- Wait for edge_kernel's atomics to be complete & visible ----
    cudaGridDependencySynchronize();

    if (active) {
        const float2 z = g_z[i];
        g_z[i] = make_float2(0.0f, 0.0f);   // restore zero-invariant for next replay

        const float h0 = fmaxf(h0x + z.x, 0.0f);
        const float h1 = fmaxf(h1x + z.y, 0.0f);
        const float o2 = h0 * w20 + h1 * w21 + bb2 + x2;

        out[i * 3 + 0] = n1 + x0;
        out[i * 3 + 1] = (n1_n2 - n1) + x1;
        out[i * 3 + 2] = o2;
    }
}

extern "C" void kernel_launch(void* const* d_in, const int* in_sizes, int n_in,
                              void* d_out, int out_size) {
    // Inputs: 0:x 1:edge_attr 2:u 3:W1 4:b1 5:W2 6:b2 7:edge_index 8:batch
    const float*  x    = (const float*)d_in[0];
    const float4* ea   = (const float4*)d_in[1];
    const float*  W1   = (const float*)d_in[3];
    const float*  b1   = (const float*)d_in[4];
    const float*  W2   = (const float*)d_in[5];
    const float*  b2   = (const float*)d_in[6];
    const int*    eidx = (const int*)d_in[7];   // int64 in reference -> int32 on device
    float*        out  = (float*)d_out;

    const int* col = eidx + N_EDGES;  // edge_index[1, :]

    edge_kernel<<<(N_EDGES + 255) / 256, 256>>>(ea, col, W1);

    // Programmatic dependent launch: node_kernel starts while edge_kernel is
    // still running, does its x-only math, then grid-syncs before reading g_z.
    cudaLaunchConfig_t cfg = {};
    cfg.gridDim  = dim3((N_NODES + 255) / 256);
    cfg.blockDim = dim3(256);
    cfg.dynamicSmemBytes = 0;
    cfg.stream = 0;
    cudaLaunchAttribute attrs[1];
    attrs[0].id = cudaLaunchAttributeProgrammaticStreamSerialization;
    attrs[0].val.programmaticStreamSerializationAllowed = 1;
    cfg.attrs = attrs;
    cfg.numAttrs = 1;
    cudaLaunchKernelEx(&cfg, node_kernel, x, W1, b1, W2, b2, out);
}